// round 4
// baseline (speedup 1.0000x reference)
#include <cuda_runtime.h>

#define D 64
#define MAXN 100000
#define CAP 32

// Static scratch (no allocs allowed):
__device__ __align__(16) float g_scratch[MAXN * D];   // 25.6 MB pre-GEMM accumulator
__device__ int d_counts[MAXN];                        // live-edge count per dst node
__device__ __align__(8) uint2 d_slots[MAXN * CAP];    // (edge_id, s_bits) buckets, 25.6 MB

// ---------------------------------------------------------------------------
// Kernel 1: place. For each live edge (drop_mask != 0, ~30%):
//   s = ci[src[e]] * dm[e];  bucket (e, s) under dst[e].
// Int atomics only (~1M spread lanes ~ 4us). Dead edges exit after one load.
// ---------------------------------------------------------------------------
__global__ void place_kernel(const float* __restrict__ ci,
                             const float* __restrict__ dm,
                             const int*   __restrict__ src,
                             const int*   __restrict__ dst,
                             int E) {
    int e = blockIdx.x * blockDim.x + threadIdx.x;
    if (e >= E) return;
    float m = dm[e];
    if (m == 0.f) return;                 // inverted dropout: exact zero, no contribution
    float s = ci[src[e]] * m;
    int d = dst[e];
    int pos = atomicAdd(&d_counts[d], 1);
    if (pos < CAP)                        // Poisson(3) deg: P(>=32) ~ 1e-22, guard anyway
        d_slots[(size_t)d * CAP + pos] = make_uint2((unsigned)e, __float_as_uint(s));
}

// ---------------------------------------------------------------------------
// Kernel 2: accumulate. 16 threads per node (one float4 lane each):
//   g[n,:] = sum_i s_i * rf[e_i,:]   over the node's bucket.
// No atomics; rf row reads are 256B coalesced; one STG.128 per lane at the end.
// Also serves as the zero-init of g (every node fully written).
// ---------------------------------------------------------------------------
__global__ void accum_kernel(const float4* __restrict__ rf, int N) {
    int gid = blockIdx.x * blockDim.x + threadIdx.x;
    int n = gid >> 4;
    if (n >= N) return;
    int q = gid & 15;

    int cnt = d_counts[n];
    if (cnt > CAP) cnt = CAP;

    float4 acc = make_float4(0.f, 0.f, 0.f, 0.f);
    const uint2* sl = &d_slots[(size_t)n * CAP];
    for (int i = 0; i < cnt; i++) {
        uint2 p = sl[i];                          // 16 lanes same addr -> broadcast
        float s = __uint_as_float(p.y);
        float4 v = rf[(size_t)p.x * 16 + q];      // coalesced 256B row read
        acc.x += s * v.x; acc.y += s * v.y;
        acc.z += s * v.z; acc.w += s * v.w;
    }
    reinterpret_cast<float4*>(g_scratch)[(size_t)n * 16 + q] = acc;
}

// ---------------------------------------------------------------------------
// Kernel 3: out = (g @ W^T) * ci
// Block: 64 rows x 64 features, 256 threads. Thread: 4 rows (ri*4..) x
// 4 features (fi*4..), register tile. Per k: ONE LDS.128 from Gt[k][.] +
// ONE LDS.128 from Wk[k][.] feeding 8 fma.rn.f32x2 (acc packed along
// feature pairs -> W pairs come directly from the float4, only g needs dup).
// ---------------------------------------------------------------------------
__global__ void gemm_scale_kernel(const float* __restrict__ W,
                                  const float* __restrict__ ci,
                                  float* __restrict__ out,
                                  int N) {
    __shared__ __align__(16) float Wk[D][68];   // Wk[k][f] = W[f][k] (rows 16B aligned)
    __shared__ __align__(16) float Gt[D][68];   // Gt[k][r]

    int tid = threadIdx.x;
    int row0 = blockIdx.x * 64;

    // Load W transposed: coalesced LDG, STS has ~4-way conflicts (cheap, 128 ops)
    #pragma unroll
    for (int i = tid; i < D * D; i += 256) {
        int f = i >> 6, k = i & 63;
        Wk[k][f] = W[i];
    }
    // Load G tile transposed (zero-pad past N)
    #pragma unroll
    for (int i = tid; i < 64 * D; i += 256) {
        int r = i >> 6, c = i & 63;
        int row = row0 + r;
        Gt[c][r] = (row < N) ? g_scratch[(size_t)row * D + c] : 0.f;
    }
    __syncthreads();

    int fi = tid & 15;          // features fi*4 .. fi*4+3
    int ri = tid >> 4;          // rows    ri*4 .. ri*4+3

    // acc[j][p]: row j (0..3), feature-pair p (0: f0f1, 1: f2f3), f32x2 packed
    unsigned long long acc[4][2];
    #pragma unroll
    for (int j = 0; j < 4; j++) { acc[j][0] = 0ull; acc[j][1] = 0ull; }

    #pragma unroll 8
    for (int k = 0; k < D; k++) {
        float4 g4 = *reinterpret_cast<const float4*>(&Gt[k][ri * 4]);
        float4 w4 = *reinterpret_cast<const float4*>(&Wk[k][fi * 4]);
        unsigned long long w01, w23;
        asm("mov.b64 %0, {%1, %2};" : "=l"(w01) : "f"(w4.x), "f"(w4.y));
        asm("mov.b64 %0, {%1, %2};" : "=l"(w23) : "f"(w4.z), "f"(w4.w));
        float gj[4] = {g4.x, g4.y, g4.z, g4.w};
        #pragma unroll
        for (int j = 0; j < 4; j++) {
            unsigned long long g2;
            asm("mov.b64 %0, {%1, %1};" : "=l"(g2) : "f"(gj[j]));
            asm("fma.rn.f32x2 %0, %1, %2, %0;" : "+l"(acc[j][0]) : "l"(w01), "l"(g2));
            asm("fma.rn.f32x2 %0, %1, %2, %0;" : "+l"(acc[j][1]) : "l"(w23), "l"(g2));
        }
    }

    #pragma unroll
    for (int j = 0; j < 4; j++) {
        int row = row0 + ri * 4 + j;
        if (row < N) {
            float c = ci[row];
            unsigned long long c2;
            asm("mov.b64 %0, {%1, %1};" : "=l"(c2) : "f"(c));
            unsigned long long r01, r23;
            asm("mul.rn.f32x2 %0, %1, %2;" : "=l"(r01) : "l"(acc[j][0]), "l"(c2));
            asm("mul.rn.f32x2 %0, %1, %2;" : "=l"(r23) : "l"(acc[j][1]), "l"(c2));
            float2 o01 = *reinterpret_cast<float2*>(&r01);
            float2 o23 = *reinterpret_cast<float2*>(&r23);
            float4 o = make_float4(o01.x, o01.y, o23.x, o23.y);
            *reinterpret_cast<float4*>(&out[(size_t)row * D + fi * 4]) = o;
        }
    }
}

// ---------------------------------------------------------------------------
// Launch
// Inputs: review_feat [E,64] f32, ci [N,1] f32, W [64,64] f32,
//         drop_mask [E,1] f32, src [E] i32, dst [E] i32.  Output: [N,64] f32
// ---------------------------------------------------------------------------
extern "C" void kernel_launch(void* const* d_in, const int* in_sizes, int n_in,
                              void* d_out, int out_size) {
    const float4* rf  = (const float4*)d_in[0];
    const float*  ci  = (const float*) d_in[1];
    const float*  W   = (const float*) d_in[2];
    const float*  dm  = (const float*) d_in[3];
    const int*    src = (const int*)   d_in[4];
    const int*    dst = (const int*)   d_in[5];
    float* out = (float*)d_out;

    int E = in_sizes[4];
    int N = in_sizes[1];

    // 1. zero the per-node counters (graph-capturable memset node)
    void* cptr = nullptr;
    cudaGetSymbolAddress(&cptr, d_counts);
    cudaMemsetAsync(cptr, 0, (size_t)N * sizeof(int), 0);

    // 2. bucket live edges by dst
    place_kernel<<<(E + 255) / 256, 256>>>(ci, dm, src, dst, E);

    // 3. per-node accumulation (atomic-free), writes g
    int athreads = N * 16;
    accum_kernel<<<(athreads + 255) / 256, 256>>>(rf, N);

    // 4. GEMM by W^T fused with final ci scale
    gemm_scale_kernel<<<(N + 63) / 64, 256>>>(W, ci, out, N);
}

// round 5
// speedup vs baseline: 1.2226x; 1.2226x over previous
#include <cuda_runtime.h>

#define D 64
#define MAXN 100000

// Scratch accumulator g[N, 64] (static __device__: no allocs allowed)
__device__ __align__(16) float g_scratch[MAXN * D];

// ---------------------------------------------------------------------------
// Scatter:  g[dst[e], :] += (ci[src[e]] * drop_mask[e]) * review_feat[e, :]
//
// Warp-cooperative (round-3 proven form, ~30us). Each warp owns 32 edges:
//   - metadata loaded coalesced (one warp-LDG per array)
//   - ballot over (dm != 0): ~70% of edges are exact zeros (inverted dropout)
//   - live edges processed two per iteration: lanes 0-15 = edge A,
//     lanes 16-31 = edge B; s/dst broadcast by shuffle; one coalesced
//     LDG.128 (2x256B) + one red.global.add.v4.f32 per iteration.
// ---------------------------------------------------------------------------
__global__ void scatter_kernel(const float4* __restrict__ rf,
                               const float*  __restrict__ ci,
                               const float*  __restrict__ dm,
                               const int*    __restrict__ src,
                               const int*    __restrict__ dst,
                               int E) {
    int warp = (blockIdx.x * blockDim.x + threadIdx.x) >> 5;
    int lane = threadIdx.x & 31;
    int ebase = warp * 32;
    int e = ebase + lane;

    float m = 0.f, s = 0.f;
    int d = 0;
    if (e < E) {
        m = dm[e];                       // coalesced
        if (m != 0.f) {
            d = dst[e];                  // coalesced (live lanes)
            s = ci[src[e]] * m;          // src coalesced, ci gathered
        }
    }
    unsigned mask = __ballot_sync(0xFFFFFFFFu, m != 0.f);

    int half = lane >> 4;                // 0: edge A, 1: edge B
    int q = lane & 15;                   // float4 index within the 64-wide row

    while (mask) {
        int l0 = __ffs(mask) - 1; mask &= mask - 1;
        int l1 = -1;
        if (mask) { l1 = __ffs(mask) - 1; mask &= mask - 1; }

        int l = half ? l1 : l0;
        int lsafe = (l >= 0) ? l : l0;   // keep shuffles warp-uniform
        float sv = __shfl_sync(0xFFFFFFFFu, s, lsafe);
        int   dv = __shfl_sync(0xFFFFFFFFu, d, lsafe);

        if (l >= 0) {
            float4 v = rf[(size_t)(ebase + l) * 16 + q];
            v.x *= sv; v.y *= sv; v.z *= sv; v.w *= sv;
            float* p = &g_scratch[(size_t)dv * D + q * 4];
            asm volatile("red.global.add.v4.f32 [%0], {%1, %2, %3, %4};"
                         :: "l"(p), "f"(v.x), "f"(v.y), "f"(v.z), "f"(v.w)
                         : "memory");
        }
    }
}

// ---------------------------------------------------------------------------
// GEMM: out = (g @ W^T) * ci   — register-blocked 4 rows x 4 features/thread.
// Block: 64 rows x 64 features, 256 threads.
// Per k: ONE LDS.128 of Gt[k][ri*4..] (2 distinct addrs/warp -> broadcast) +
// ONE LDS.128 of Wk[k][fi*4..] (16 distinct 16B addrs -> conflict-free),
// feeding 8 fma.rn.f32x2 (acc packed along feature pairs, so W pairs come
// straight from the float4 -> only g needs a dup mov).
// 128 LDS + 512 FMA2 per thread => FMA-pipe bound, ~12-13us.
// ---------------------------------------------------------------------------
__global__ void gemm_scale_kernel(const float* __restrict__ W,
                                  const float* __restrict__ ci,
                                  float* __restrict__ out,
                                  int N) {
    __shared__ __align__(16) float Wk[D][68];   // Wk[k][f] = W[f][k] (rows 16B aligned)
    __shared__ __align__(16) float Gt[D][68];   // Gt[k][r]

    int tid = threadIdx.x;
    int row0 = blockIdx.x * 64;

    #pragma unroll
    for (int i = tid; i < D * D; i += 256) {
        int f = i >> 6, k = i & 63;
        Wk[k][f] = W[i];                 // coalesced LDG; 4-way STS conflict (cheap)
    }
    #pragma unroll
    for (int i = tid; i < 64 * D; i += 256) {
        int r = i >> 6, c = i & 63;
        int row = row0 + r;
        Gt[c][r] = (row < N) ? g_scratch[(size_t)row * D + c] : 0.f;
    }
    __syncthreads();

    int fi = tid & 15;          // features fi*4 .. fi*4+3
    int ri = tid >> 4;          // rows    ri*4 .. ri*4+3

    // acc[j][p]: row j (0..3), feature-pair p (0: f0f1, 1: f2f3), f32x2 packed
    unsigned long long acc[4][2];
    #pragma unroll
    for (int j = 0; j < 4; j++) { acc[j][0] = 0ull; acc[j][1] = 0ull; }

    #pragma unroll 8
    for (int k = 0; k < D; k++) {
        float4 g4 = *reinterpret_cast<const float4*>(&Gt[k][ri * 4]);
        float4 w4 = *reinterpret_cast<const float4*>(&Wk[k][fi * 4]);
        unsigned long long w01, w23;
        asm("mov.b64 %0, {%1, %2};" : "=l"(w01) : "f"(w4.x), "f"(w4.y));
        asm("mov.b64 %0, {%1, %2};" : "=l"(w23) : "f"(w4.z), "f"(w4.w));
        float gj[4] = {g4.x, g4.y, g4.z, g4.w};
        #pragma unroll
        for (int j = 0; j < 4; j++) {
            unsigned long long g2;
            asm("mov.b64 %0, {%1, %1};" : "=l"(g2) : "f"(gj[j]));
            asm("fma.rn.f32x2 %0, %1, %2, %0;" : "+l"(acc[j][0]) : "l"(w01), "l"(g2));
            asm("fma.rn.f32x2 %0, %1, %2, %0;" : "+l"(acc[j][1]) : "l"(w23), "l"(g2));
        }
    }

    #pragma unroll
    for (int j = 0; j < 4; j++) {
        int row = row0 + ri * 4 + j;
        if (row < N) {
            float c = ci[row];
            unsigned long long c2;
            asm("mov.b64 %0, {%1, %1};" : "=l"(c2) : "f"(c));
            unsigned long long r01, r23;
            asm("mul.rn.f32x2 %0, %1, %2;" : "=l"(r01) : "l"(acc[j][0]), "l"(c2));
            asm("mul.rn.f32x2 %0, %1, %2;" : "=l"(r23) : "l"(acc[j][1]), "l"(c2));
            float2 o01 = *reinterpret_cast<float2*>(&r01);
            float2 o23 = *reinterpret_cast<float2*>(&r23);
            float4 o = make_float4(o01.x, o01.y, o23.x, o23.y);
            *reinterpret_cast<float4*>(&out[(size_t)row * D + fi * 4]) = o;
        }
    }
}

// ---------------------------------------------------------------------------
// Launch
// Inputs: review_feat [E,64] f32, ci [N,1] f32, W [64,64] f32,
//         drop_mask [E,1] f32, src [E] i32, dst [E] i32.  Output: [N,64] f32
// ---------------------------------------------------------------------------
extern "C" void kernel_launch(void* const* d_in, const int* in_sizes, int n_in,
                              void* d_out, int out_size) {
    const float4* rf  = (const float4*)d_in[0];
    const float*  ci  = (const float*) d_in[1];
    const float*  W   = (const float*) d_in[2];
    const float*  dm  = (const float*) d_in[3];
    const int*    src = (const int*)   d_in[4];
    const int*    dst = (const int*)   d_in[5];
    float* out = (float*)d_out;

    int E = in_sizes[4];
    int N = in_sizes[1];

    // 1. zero scratch accumulator (graph-capturable memset node)
    void* gptr = nullptr;
    cudaGetSymbolAddress(&gptr, g_scratch);
    cudaMemsetAsync(gptr, 0, (size_t)N * D * sizeof(float), 0);

    // 2. warp-cooperative scatter-accumulate (dropout-sparse, REDG.v4)
    int warps = (E + 31) / 32;
    int sblocks = (warps * 32 + 255) / 256;
    scatter_kernel<<<sblocks, 256>>>(rf, ci, dm, src, dst, E);

    // 3. GEMM by W^T fused with final ci scale (register-blocked f32x2)
    gemm_scale_kernel<<<(N + 63) / 64, 256>>>(W, ci, out, N);
}